// round 17
// baseline (speedup 1.0000x reference)
#include <cuda_runtime.h>
#include <cuda_fp16.h>
#include <stdint.h>
#include <math.h>

#define HID 1024
#define NH 16
#define HD 64
#define BLK 64
#define MAXM 16384
#define NEGV -1000000000.0f

// Scratch (device globals: no allocations allowed)
__device__ __half g_q[MAXM * HID];
__device__ __half g_k[MAXM * HID];
__device__ __half g_v[MAXM * HID];
__device__ float  g_y[MAXM * HID];
__device__ __half g_xh[MAXM * HID];
__device__ __half g_ch[MAXM * HID];
__device__ __half g_whq[HID * HID];
__device__ __half g_whk[HID * HID];
__device__ __half g_whv[HID * HID];
__device__ __half g_who[HID * HID];

// ---------------------------------------------------------------------------
// helpers
// ---------------------------------------------------------------------------
__device__ __forceinline__ uint32_t h2_bits(__half2 h) {
    union { __half2 h; uint32_t u; } cvt;
    cvt.h = h;
    return cvt.u;
}
__device__ __forceinline__ __half2 bits_h2(uint32_t u) {
    union { __half2 h; uint32_t u; } cvt;
    cvt.u = u;
    return cvt.h;
}

__device__ __forceinline__ void mma16(float* c, const uint32_t* a, const uint32_t* b) {
    asm volatile(
        "mma.sync.aligned.m16n8k16.row.col.f32.f16.f16.f32 "
        "{%0,%1,%2,%3}, {%4,%5,%6,%7}, {%8,%9}, {%0,%1,%2,%3};"
        : "+f"(c[0]), "+f"(c[1]), "+f"(c[2]), "+f"(c[3])
        : "r"(a[0]), "r"(a[1]), "r"(a[2]), "r"(a[3]), "r"(b[0]), "r"(b[1]));
}

__device__ __forceinline__ void ldsm4(uint32_t* r, uint32_t addr) {
    asm volatile("ldmatrix.sync.aligned.m8n8.x4.shared.b16 {%0,%1,%2,%3}, [%4];"
                 : "=r"(r[0]), "=r"(r[1]), "=r"(r[2]), "=r"(r[3]) : "r"(addr));
}

__device__ __forceinline__ void ldsm4t(uint32_t* r, uint32_t addr) {
    asm volatile("ldmatrix.sync.aligned.m8n8.x4.trans.shared.b16 {%0,%1,%2,%3}, [%4];"
                 : "=r"(r[0]), "=r"(r[1]), "=r"(r[2]), "=r"(r[3]) : "r"(addr));
}

__device__ __forceinline__ void cpasync16(uint32_t dst, const void* src) {
    asm volatile("cp.async.cg.shared.global [%0], [%1], 16;" :: "r"(dst), "l"(src));
}
__device__ __forceinline__ void cpcommit() { asm volatile("cp.async.commit_group;"); }
template <int N> __device__ __forceinline__ void cpwait() {
    asm volatile("cp.async.wait_group %0;" :: "n"(N));
}

// ---------------------------------------------------------------------------
// fp32 -> fp16 conversion (16 elems/thread)
// ---------------------------------------------------------------------------
__device__ __forceinline__ void cvt16(const float* in, __half* out, int i)
{
    float4 a0 = ((const float4*)in)[4 * i + 0];
    float4 b0 = ((const float4*)in)[4 * i + 1];
    float4 a1 = ((const float4*)in)[4 * i + 2];
    float4 b1 = ((const float4*)in)[4 * i + 3];
    uint4 v0 = make_uint4(h2_bits(__floats2half2_rn(a0.x, a0.y)),
                          h2_bits(__floats2half2_rn(a0.z, a0.w)),
                          h2_bits(__floats2half2_rn(b0.x, b0.y)),
                          h2_bits(__floats2half2_rn(b0.z, b0.w)));
    uint4 v1 = make_uint4(h2_bits(__floats2half2_rn(a1.x, a1.y)),
                          h2_bits(__floats2half2_rn(a1.z, a1.w)),
                          h2_bits(__floats2half2_rn(b1.x, b1.y)),
                          h2_bits(__floats2half2_rn(b1.z, b1.w)));
    ((uint4*)out)[2 * i + 0] = v0;
    ((uint4*)out)[2 * i + 1] = v1;
}

__global__ void __launch_bounds__(256)
cvt_kernel(const float* __restrict__ in, __half* __restrict__ out, int n16)
{
    int i = blockIdx.x * blockDim.x + threadIdx.x;
    if (i < n16) cvt16(in, out, i);
}

__global__ void __launch_bounds__(256)
cvt4_kernel(const float* __restrict__ w0, const float* __restrict__ w1,
            const float* __restrict__ w2, const float* __restrict__ w3,
            __half* __restrict__ o0, __half* __restrict__ o1,
            __half* __restrict__ o2, __half* __restrict__ o3, int n16)
{
    int i = blockIdx.x * blockDim.x + threadIdx.x;
    int sel = i / n16;
    int j = i - sel * n16;
    const float* in = (sel == 0) ? w0 : (sel == 1) ? w1 : (sel == 2) ? w2 : w3;
    __half* out     = (sel == 0) ? o0 : (sel == 1) ? o1 : (sel == 2) ? o2 : o3;
    cvt16(in, out, j);
}

// ---------------------------------------------------------------------------
// fp16 tensor-core GEMM: 128x128 CTA tile, 128 threads (4 warps, 2M x 2N),
// 64x64 WARP tile -> 8 LDSM / 32 HMMA per k16 (mma/LDSM = 4.0).
// 3-stage cp.async pipeline, k-chunk 64.
// MODE 0: z-fused QKV, out = __half, transposed [(b*NH+h)*S + t]*64 + d
// MODE 1: O-proj,    out = float, row-major + residual
// ---------------------------------------------------------------------------
#define KC 64
#define ST 36
#define NSTG 3
#define GEMM_SMEM (NSTG * 2 * 128 * ST * 4)
#define NCH16 (HID / KC)

template <int MODE>
__global__ void __launch_bounds__(128, 2)
gemm_fp16(const __half* __restrict__ X,
          const __half* __restrict__ W0, const __half* __restrict__ W1,
          const __half* __restrict__ W2,
          const float* __restrict__ B0, const float* __restrict__ B1,
          const float* __restrict__ B2,
          const float* __restrict__ resid,
          void* __restrict__ O0, void* __restrict__ O1, void* __restrict__ O2,
          int M, int S)
{
    extern __shared__ uint32_t smem[];

    const int z = (MODE == 0) ? blockIdx.z : 0;
    const __half* W   = (z == 0) ? W0 : (z == 1) ? W1 : W2;
    const float* bias = (z == 0) ? B0 : (z == 1) ? B1 : B2;
    void*        out  = (z == 0) ? O0 : (z == 1) ? O1 : O2;

    const int tid  = threadIdx.x;
    const int lane = tid & 31;
    const int wid  = tid >> 5;
    const int gid  = lane >> 2;
    const int tig  = lane & 3;
    const int wm   = wid & 1;     // 2 warps along M (64 rows each)
    const int wn   = wid >> 1;    // 2 warps along N (64 cols each)
    const int mBase = blockIdx.y * 128;
    const int nBase = blockIdx.x * 128;

    const uint32_t sbase = (uint32_t)__cvta_generic_to_shared(smem);
    const int lrow = tid >> 3;            // 0..15
    const int lq4  = (tid & 7) << 2;
    const int lq8  = (tid & 7) << 3;

    const int lr8 = lane & 7;
    const uint32_t aOff = (uint32_t)((wm * 64 + lr8 + ((lane >> 3) & 1) * 8) * 144 +
                                     ((lane >> 4) & 1) * 16);
    const uint32_t bOff = (uint32_t)((wn * 64 + lr8 + ((lane >> 4) & 1) * 8) * 144 +
                                     ((lane >> 3) & 1) * 16);

    auto issue_load = [&](int chunk) {
        int s = chunk % NSTG;
        uint32_t dA = sbase + (uint32_t)(s * 2 * 128 * ST * 4);
        uint32_t dB = dA + (uint32_t)(128 * ST * 4);
        int kc = chunk * KC;
#pragma unroll
        for (int i = 0; i < 8; ++i) {
            int r = lrow + i * 16;
            cpasync16(dA + (uint32_t)((r * ST + lq4) * 4),
                      X + (size_t)(mBase + r) * HID + kc + lq8);
            cpasync16(dB + (uint32_t)((r * ST + lq4) * 4),
                      W + (size_t)(nBase + r) * HID + kc + lq8);
        }
        cpcommit();
    };

    float acc[4][8][4];
#pragma unroll
    for (int mt = 0; mt < 4; ++mt)
#pragma unroll
        for (int nt = 0; nt < 8; ++nt)
#pragma unroll
            for (int j = 0; j < 4; ++j) acc[mt][nt][j] = 0.f;

    issue_load(0);
    issue_load(1);

    for (int c = 0; c < NCH16; ++c) {
        cpwait<1>();
        __syncthreads();
        if (c + 2 < NCH16) issue_load(c + 2);

        const uint32_t pA = sbase + (uint32_t)((c % NSTG) * 2 * 128 * ST * 4);
        const uint32_t pB = pA + (uint32_t)(128 * ST * 4);
#pragma unroll
        for (int ks = 0; ks < 4; ++ks) {
            uint32_t af[4][4], bfr[16];
#pragma unroll
            for (int mt = 0; mt < 4; ++mt)
                ldsm4(af[mt], pA + aOff + (uint32_t)(mt * 16 * 144 + ks * 32));
#pragma unroll
            for (int np = 0; np < 4; ++np)
                ldsm4(bfr + np * 4, pB + bOff + (uint32_t)(np * 16 * 144 + ks * 32));
#pragma unroll
            for (int mt = 0; mt < 4; ++mt)
#pragma unroll
                for (int nt = 0; nt < 8; ++nt)
                    mma16(acc[mt][nt], af[mt], bfr + nt * 2);
        }
    }
    __syncthreads();

    // epilogue
#pragma unroll
    for (int mt = 0; mt < 4; ++mt)
#pragma unroll
        for (int i = 0; i < 2; ++i) {
            int m = mBase + wm * 64 + mt * 16 + gid + i * 8;
#pragma unroll
            for (int nt = 0; nt < 8; ++nt) {
                int n = nBase + wn * 64 + nt * 8 + 2 * tig;
                float v0 = acc[mt][nt][i * 2 + 0] + bias[n];
                float v1 = acc[mt][nt][i * 2 + 1] + bias[n + 1];
                if (MODE == 0) {
                    int bb = m / S;
                    int t = m - bb * S;
                    int h = n >> 6;
                    int d = n & 63;
                    __half* o = (__half*)out + ((size_t)(bb * NH + h) * S + t) * HD + d;
                    *(__half2*)o = __floats2half2_rn(v0, v1);
                } else {
                    size_t off = (size_t)m * HID + n;
                    float2 rr = *(const float2*)(resid + off);
                    *(float2*)((float*)out + off) = make_float2(v0 + rr.x, v1 + rr.y);
                }
            }
        }
}

// ---------------------------------------------------------------------------
// Block-sparse attention (unchanged from best round): fp16 mma, register Q,
// batched cp.async K/V staging, register softmax.
// ---------------------------------------------------------------------------
#define QS_OFF   0
#define KV_OFF   9216
#define PP_OFF   46080
#define AM_OFF   79872
#define RED_OFF  80896
#define SINV_OFF 81920
#define ATTN_SMEM 82176
#define PPST 132
#define SOFT_SHIFT 8.0f

__global__ void __launch_bounds__(256, 2)
attn_fp16(const __half* __restrict__ gq, const __half* __restrict__ gk,
          const __half* __restrict__ gv, const float* __restrict__ mask,
          __half* __restrict__ gctx, int S, int nblk)
{
    extern __shared__ char smc[];
    uint32_t* pp  = (uint32_t*)(smc + PP_OFF);
    float*    am  = (float*)(smc + AM_OFF);
    float*    red = (float*)(smc + RED_OFF);
    float*    sinv= (float*)(smc + SINV_OFF);

    const int tid  = threadIdx.x;
    const int lane = tid & 31;
    const int wid  = tid >> 5;
    const int gid  = lane >> 2;
    const int tig  = lane & 3;
    const int wm   = wid >> 2;
    const int wn   = wid & 3;

    const uint32_t sb = (uint32_t)__cvta_generic_to_shared(smc);
    const int lr8 = lane & 7;
    const uint32_t aOff144 = (uint32_t)((wm * 32 + lr8 + ((lane >> 3) & 1) * 8) * 144 +
                                        ((lane >> 4) & 1) * 16);
    const uint32_t bOff144 = (uint32_t)((wn * 16 + lr8 + ((lane >> 4) & 1) * 8) * 144 +
                                        ((lane >> 3) & 1) * 16);
    const uint32_t vOff144 = (uint32_t)((lr8 + ((lane >> 3) & 1) * 8) * 144 +
                                        (wn * 16 + ((lane >> 4) & 1) * 8) * 2);
    const uint32_t aOffPP  = (uint32_t)(PP_OFF +
                                        (wm * 32 + lr8 + ((lane >> 3) & 1) * 8) * (PPST * 4) +
                                        ((lane >> 4) & 1) * 16);

    const int qb = blockIdx.x % nblk;
    const int bh = blockIdx.x / nblk;
    const int b  = bh >> 4;
    const int h  = bh & 15;

    int cnd[4] = {0, qb - 1, qb, qb + 1};
    int kbi[4], vld[4];
#pragma unroll
    for (int c = 0; c < 4; ++c) {
        int cc = cnd[c];
        int ok = (cc >= 0 && cc < nblk);
#pragma unroll
        for (int j = 0; j < 4; ++j)
            if (j < c && vld[j] && cnd[j] == cc) ok = 0;
        vld[c] = ok;
        kbi[c] = min(max(cc, 0), nblk - 1);
    }

    const size_t bhS = (size_t)bh * S;

    // issue cp.async for ALL 4 K blocks
#pragma unroll
    for (int m = 0; m < 4; ++m) {
        const __half* kp = gk + (bhS + (size_t)kbi[m] * BLK) * HD;
#pragma unroll
        for (int j = 0; j < 2; ++j) {
            int u = tid + j * 256;
            cpasync16(sb + KV_OFF + (uint32_t)((m * 64 + (u >> 3)) * 144 + (u & 7) * 16),
                      kp + (size_t)u * 8);
        }
    }
    cpcommit();

    // stage Q (scaled 1/8) + mask rows
    {
        const uint4* qptr = (const uint4*)(gq + (bhS + (size_t)qb * BLK) * HD);
        const __half2 sc8 = __floats2half2_rn(0.125f, 0.125f);
#pragma unroll
        for (int j = 0; j < 2; ++j) {
            int u = tid + j * 256;
            uint4 v = qptr[u];
            v.x = h2_bits(__hmul2(bits_h2(v.x), sc8));
            v.y = h2_bits(__hmul2(bits_h2(v.y), sc8));
            v.z = h2_bits(__hmul2(bits_h2(v.z), sc8));
            v.w = h2_bits(__hmul2(bits_h2(v.w), sc8));
            *(uint4*)(smc + QS_OFF + ((u >> 3) * 36 + (u & 7) * 4) * 4) = v;
        }
        int m = tid >> 6, c = tid & 63;
        am[tid] = vld[m] ? mask[(size_t)b * S + (size_t)kbi[m] * BLK + c] : NEGV;
    }

    cpwait<0>();
    __syncthreads();

    // hoist Q fragments into registers
    uint32_t qf[2][4][4];
#pragma unroll
    for (int mt = 0; mt < 2; ++mt)
#pragma unroll
        for (int ks = 0; ks < 4; ++ks)
            ldsm4(qf[mt][ks], sb + QS_OFF + aOff144 + (uint32_t)(mt * 16 * 144 + ks * 32));

    // ---- scores + register softmax ----
    float rowsum[2][2] = {{0.f, 0.f}, {0.f, 0.f}};
#pragma unroll
    for (int m = 0; m < 4; ++m) {
        if (vld[m]) {
            float acc[2][2][4] = {};
#pragma unroll
            for (int ks = 0; ks < 4; ++ks) {
                uint32_t bfr[4];
                ldsm4(bfr, sb + KV_OFF + (uint32_t)(m * 64 * 144) + bOff144 + ks * 32);
#pragma unroll
                for (int mt = 0; mt < 2; ++mt)
#pragma unroll
                    for (int nt = 0; nt < 2; ++nt)
                        mma16(acc[mt][nt], qf[mt][ks], bfr + nt * 2);
            }
#pragma unroll
            for (int mt = 0; mt < 2; ++mt)
#pragma unroll
                for (int i = 0; i < 2; ++i) {
                    int r = wm * 32 + mt * 16 + gid + i * 8;
#pragma unroll
                    for (int nt = 0; nt < 2; ++nt) {
                        int c = wn * 16 + nt * 8 + 2 * tig;
                        float aval = am[m * 64 + c];
                        float e0 = __expf(acc[mt][nt][i * 2 + 0] + aval - SOFT_SHIFT);
                        float e1 = __expf(acc[mt][nt][i * 2 + 1] + aval - SOFT_SHIFT);
                        rowsum[mt][i] += e0 + e1;
                        pp[r * PPST + m * 32 + wn * 8 + nt * 4 + tig] =
                            h2_bits(__floats2half2_rn(e0, e1));
                    }
                }
        } else {
#pragma unroll
            for (int mt = 0; mt < 2; ++mt)
#pragma unroll
                for (int i = 0; i < 2; ++i) {
                    int r = wm * 32 + mt * 16 + gid + i * 8;
#pragma unroll
                    for (int nt = 0; nt < 2; ++nt)
                        pp[r * PPST + m * 32 + wn * 8 + nt * 4 + tig] = 0u;
                }
        }
    }

    __syncthreads();   // all K reads done -> kv reusable for V

    // issue cp.async for ALL 4 V blocks
#pragma unroll
    for (int m = 0; m < 4; ++m) {
        const __half* vp = gv + (bhS + (size_t)kbi[m] * BLK) * HD;
#pragma unroll
        for (int j = 0; j < 2; ++j) {
            int u = tid + j * 256;
            cpasync16(sb + KV_OFF + (uint32_t)((m * 64 + (u >> 3)) * 144 + (u & 7) * 16),
                      vp + (size_t)u * 8);
        }
    }
    cpcommit();

    // cross-warp row-sum reduction while V loads fly
#pragma unroll
    for (int mt = 0; mt < 2; ++mt)
#pragma unroll
        for (int i = 0; i < 2; ++i) {
            float s = rowsum[mt][i];
            s += __shfl_xor_sync(0xffffffffu, s, 1);
            s += __shfl_xor_sync(0xffffffffu, s, 2);
            if (tig == 0) {
                int r = wm * 32 + mt * 16 + gid + i * 8;
                red[wn * 64 + r] = s;
            }
        }

    cpwait<0>();
    __syncthreads();
    if (tid < 64)
        sinv[tid] = 1.f / (red[tid] + red[64 + tid] + red[128 + tid] + red[192 + tid]);

    // ---- ctx = P @ V ----
    float ctx[2][2][4] = {};
#pragma unroll
    for (int m = 0; m < 4; ++m) {
        if (vld[m]) {
#pragma unroll
            for (int ks = 0; ks < 4; ++ks) {
                uint32_t af[2][4], bfr[4];
                ldsm4(af[0], sb + aOffPP + (uint32_t)(m * 128 + ks * 32));
                ldsm4(af[1], sb + aOffPP + (uint32_t)(16 * PPST * 4 + m * 128 + ks * 32));
                ldsm4t(bfr,  sb + KV_OFF + (uint32_t)(m * 64 * 144) + vOff144 +
                             (uint32_t)(ks * 16 * 144));
#pragma unroll
                for (int mt = 0; mt < 2; ++mt)
#pragma unroll
                    for (int nt = 0; nt < 2; ++nt)
                        mma16(ctx[mt][nt], af[mt], bfr + nt * 2);
            }
        }
    }

    __syncthreads();

    // write ctx * inv as fp16 for the O-projection GEMM
#pragma unroll
    for (int mt = 0; mt < 2; ++mt)
#pragma unroll
        for (int i = 0; i < 2; ++i) {
            int r = wm * 32 + mt * 16 + gid + i * 8;
            float iv = sinv[r];
            int t = qb * BLK + r;
            __half* o = gctx + ((size_t)(b * S + t)) * HID + h * HD;
#pragma unroll
            for (int nt = 0; nt < 2; ++nt) {
                int c = wn * 16 + nt * 8 + 2 * tig;
                *(__half2*)(o + c) = __floats2half2_rn(ctx[mt][nt][i * 2 + 0] * iv,
                                                       ctx[mt][nt][i * 2 + 1] * iv);
            }
        }
}

// ---------------------------------------------------------------------------
// LayerNorm: one CTA (256 threads) per row of 1024.
// ---------------------------------------------------------------------------
__device__ __forceinline__ float blockReduceSum(float v)
{
    __shared__ float red[8];
    __syncthreads();
    const int lane = threadIdx.x & 31;
    const int wid = threadIdx.x >> 5;
#pragma unroll
    for (int o = 16; o; o >>= 1) v += __shfl_xor_sync(0xffffffffu, v, o);
    if (lane == 0) red[wid] = v;
    __syncthreads();
    float t = (lane < 8) ? red[lane] : 0.f;
    if (wid == 0) {
#pragma unroll
        for (int o = 4; o; o >>= 1) t += __shfl_xor_sync(0xffffffffu, t, o);
        if (lane == 0) red[0] = t;
    }
    __syncthreads();
    return red[0];
}

__global__ void __launch_bounds__(256)
ln_kernel(const float* __restrict__ y, const float* __restrict__ g,
          const float* __restrict__ bt, float* __restrict__ out)
{
    const int row = blockIdx.x;
    const int t = threadIdx.x;
    float4 v = ((const float4*)(y + (size_t)row * HID))[t];

    float s = v.x + v.y + v.z + v.w;
    float mu = blockReduceSum(s) * (1.0f / HID);

    float dx = v.x - mu, dy = v.y - mu, dz = v.z - mu, dw = v.w - mu;
    float sq = dx * dx + dy * dy + dz * dz + dw * dw;
    float var = blockReduceSum(sq) * (1.0f / HID);
    float invs = rsqrtf(var + 1e-12f);

    float4 gg = ((const float4*)g)[t];
    float4 bb = ((const float4*)bt)[t];
    float4 o;
    o.x = dx * invs * gg.x + bb.x;
    o.y = dy * invs * gg.y + bb.y;
    o.z = dz * invs * gg.z + bb.z;
    o.w = dw * invs * gg.w + bb.w;
    ((float4*)(out + (size_t)row * HID))[t] = o;
}

// ---------------------------------------------------------------------------
extern "C" void kernel_launch(void* const* d_in, const int* in_sizes, int n_in,
                              void* d_out, int out_size)
{
    const float* hidden = (const float*)d_in[0];
    const float* mask   = (const float*)d_in[1];
    const float* wq = (const float*)d_in[2];
    const float* bq = (const float*)d_in[3];
    const float* wk = (const float*)d_in[4];
    const float* bk = (const float*)d_in[5];
    const float* wv = (const float*)d_in[6];
    const float* bv = (const float*)d_in[7];
    const float* wo = (const float*)d_in[8];
    const float* bo = (const float*)d_in[9];
    const float* lng = (const float*)d_in[10];
    const float* lnb = (const float*)d_in[11];

    const int M = in_sizes[1];   // b * s = 16384
    const int S = 4096;
    const int B = M / S;
    const int nblk = S / BLK;

    float *py;
    __half *pq, *pk, *pv, *pxh, *pch, *pwq, *pwk, *pwv, *pwo;
    cudaGetSymbolAddress((void**)&pq, g_q);
    cudaGetSymbolAddress((void**)&pk, g_k);
    cudaGetSymbolAddress((void**)&pv, g_v);
    cudaGetSymbolAddress((void**)&py, g_y);
    cudaGetSymbolAddress((void**)&pxh, g_xh);
    cudaGetSymbolAddress((void**)&pch, g_ch);
    cudaGetSymbolAddress((void**)&pwq, g_whq);
    cudaGetSymbolAddress((void**)&pwk, g_whk);
    cudaGetSymbolAddress((void**)&pwv, g_whv);
    cudaGetSymbolAddress((void**)&pwo, g_who);

    cudaFuncSetAttribute(gemm_fp16<0>, cudaFuncAttributeMaxDynamicSharedMemorySize, GEMM_SMEM);
    cudaFuncSetAttribute(gemm_fp16<1>, cudaFuncAttributeMaxDynamicSharedMemorySize, GEMM_SMEM);
    cudaFuncSetAttribute(attn_fp16, cudaFuncAttributeMaxDynamicSharedMemorySize, ATTN_SMEM);

    // fp32 -> fp16 conversions
    const int nHid16 = (M * HID) / 16;
    const int nW16 = (HID * HID) / 16;
    cvt_kernel<<<(nHid16 + 255) / 256, 256>>>(hidden, pxh, nHid16);
    cvt4_kernel<<<(4 * nW16 + 255) / 256, 256>>>(wq, wk, wv, wo,
                                                 pwq, pwk, pwv, pwo, nW16);

    // fused QKV: grid.z selects weight/out; outputs fp16 (128 threads/CTA)
    dim3 gridQKV(HID / 128, M / 128, 3);
    gemm_fp16<0><<<gridQKV, 128, GEMM_SMEM>>>(pxh, pwq, pwk, pwv, bq, bk, bv,
                                              nullptr, pq, pk, pv, M, S);

    attn_fp16<<<B * NH * nblk, 256, ATTN_SMEM>>>(pq, pk, pv, mask, pch, S, nblk);

    dim3 gridO(HID / 128, M / 128, 1);
    gemm_fp16<1><<<gridO, 128, GEMM_SMEM>>>(pch, pwo, nullptr, nullptr, bo, nullptr,
                                            nullptr, hidden, py, nullptr, nullptr, M, S);

    ln_kernel<<<M, 256>>>(py, lng, lnb, (float*)d_out);
}